// round 2
// baseline (speedup 1.0000x reference)
#include <cuda_runtime.h>
#include <math.h>

// ---------------- problem constants ----------------
#define BB 32      // batch
#define NN 32      // parts
#define EE 256     // encoded part size
#define HH 1500    // hidden
#define G4 6000    // 4*H
#define PP 496     // pairs
#define Q1S 600
#define QS 300
#define EV1S 1000
#define EV2S 100
#define EV3S 10
#define MPAIR (BB*PP)   // 15872
#define MNB (NN*BB)     // 1024

// ---------------- device scratch (static; no allocation) ----------------
__device__ float d_S[MNB*EE];           // sorted seq [t][b][e]
__device__ float d_xp[MNB*G4];          // x projections [t*32+b][6000]
__device__ float d_h[2][BB*HH];
__device__ float d_c[BB*HH];
__device__ float d_gpart[4][BB*G4];     // k-split partials of h@w_hh^T
__device__ float d_q1beff[Q1S];
__device__ int   d_pi[PP], d_pj[PP];
__device__ float d_Aq[MNB*Q1S];
__device__ float d_Bq[MNB*Q1S];
__device__ float d_pt[BB*EV1S];
__device__ float d_q2[MPAIR*QS];
__device__ float d_e1buf[(size_t)MPAIR*EV1S];
__device__ float d_e2buf[MPAIR*EV2S];

// ---------------- sort kernel: per (b,e) sort 32 values along parts ----------------
__global__ void k_sort(const float* __restrict__ x) {
    int tid = blockIdx.x * blockDim.x + threadIdx.x;   // 0..8191
    int b = tid >> 8, e = tid & 255;
    float v[32];
    #pragma unroll
    for (int t = 0; t < 32; t++) v[t] = x[(b * 32 + t) * EE + e];
    for (int a = 1; a < 32; a++) {
        float key = v[a];
        int c = a - 1;
        while (c >= 0 && v[c] > key) { v[c + 1] = v[c]; c--; }
        v[c + 1] = key;
    }
    #pragma unroll
    for (int t = 0; t < 32; t++) d_S[(t * 32 + b) * EE + e] = v[t];
}

// ---------------- init: pair indices, effective q1 bias, zero h/c ----------------
__global__ void k_init(const float* __restrict__ q1_w, const float* __restrict__ q1_b) {
    int idx = blockIdx.x * blockDim.x + threadIdx.x;
    if (idx < PP) {
        int p = idx, i = 0, cnt = 31;
        while (p >= cnt) { p -= cnt; i++; cnt--; }
        d_pi[idx] = i; d_pj[idx] = i + 1 + p;
    } else if (idx < PP + Q1S) {
        int o = idx - PP;
        float s = q1_b[o];
        for (int d = 1; d < 2 * EE; d += 2) s += q1_w[o * (2 * EE) + d];  // pe cos(0)=1 on odd dims
        d_q1beff[o] = s;
    } else {
        int z = idx - (PP + Q1S);
        if (z < BB * HH)                d_h[0][z] = 0.f;
        else if (z < 2 * BB * HH)       d_h[1][z - BB * HH] = 0.f;
        else if (z < 3 * BB * HH)       d_c[z - 2 * BB * HH] = 0.f;
    }
}

// ---------------- generic tiled GEMM (NT): C = act(A[M,K] @ W[N,K]^T + ...) ----------------
// grid.z > 1 splits K; partials written to C + z*M*N (bias/relu must be off then).
template<int BM>
__global__ void gemm_nt(const float* __restrict__ A, int lda,
                        const float* __restrict__ W, int ldw,
                        const float* __restrict__ bias0, const float* __restrict__ bias1,
                        const float* __restrict__ rowterm, int rowdiv,
                        float* __restrict__ C,
                        int M, int Nn, int K, int relu)
{
    constexpr int BN = 64, BK = 16;
    constexpr int THREADS = BM * 4;            // (BM/4)*(BN/4)
    constexpr int ALD = (BM * BK) / THREADS;   // 4
    constexpr int WLD = (BN * BK) / THREADS;   // 4 (BM=64) or 8 (BM=32)

    __shared__ float As[BK][BM + 1];
    __shared__ float Ws[BK][BN + 1];

    int ksplits = gridDim.z;
    int kchunk = (K + ksplits - 1) / ksplits;
    int k0 = blockIdx.z * kchunk;
    int k1 = min(K, k0 + kchunk);
    float* Cz = C + (size_t)blockIdx.z * M * Nn;

    int m0 = blockIdx.y * BM, n0 = blockIdx.x * BN;
    int tid = threadIdx.x;
    int ty = tid / 16, tx = tid % 16;

    float acc[4][4];
    #pragma unroll
    for (int i = 0; i < 4; i++)
        #pragma unroll
        for (int j = 0; j < 4; j++) acc[i][j] = 0.f;

    for (int kk = k0; kk < k1; kk += BK) {
        #pragma unroll
        for (int r = 0; r < ALD; r++) {
            int idx = tid + r * THREADS;
            int row = idx >> 4, col = idx & 15;
            int gm = m0 + row, gk = kk + col;
            As[col][row] = (gm < M && gk < k1) ? A[(size_t)gm * lda + gk] : 0.f;
        }
        #pragma unroll
        for (int r = 0; r < WLD; r++) {
            int idx = tid + r * THREADS;
            int row = idx >> 4, col = idx & 15;
            int gn = n0 + row, gk = kk + col;
            Ws[col][row] = (gn < Nn && gk < k1) ? W[(size_t)gn * ldw + gk] : 0.f;
        }
        __syncthreads();
        #pragma unroll
        for (int k = 0; k < BK; k++) {
            float a[4], b[4];
            #pragma unroll
            for (int i = 0; i < 4; i++) a[i] = As[k][ty * 4 + i];
            #pragma unroll
            for (int j = 0; j < 4; j++) b[j] = Ws[k][tx * 4 + j];
            #pragma unroll
            for (int i = 0; i < 4; i++)
                #pragma unroll
                for (int j = 0; j < 4; j++) acc[i][j] = fmaf(a[i], b[j], acc[i][j]);
        }
        __syncthreads();
    }

    #pragma unroll
    for (int i = 0; i < 4; i++) {
        int gm = m0 + ty * 4 + i;
        if (gm >= M) continue;
        #pragma unroll
        for (int j = 0; j < 4; j++) {
            int gn = n0 + tx * 4 + j;
            if (gn >= Nn) continue;
            float v = acc[i][j];
            if (bias0)   v += bias0[gn];
            if (bias1)   v += bias1[gn];
            if (rowterm) v += rowterm[(gm / rowdiv) * Nn + gn];
            if (relu)    v = fmaxf(v, 0.f);
            Cz[(size_t)gm * Nn + gn] = v;
        }
    }
}

// ---------------- q2 GEMM with fused pair construction ----------------
// A[m,k] = relu(Aq[b,i,k] + Bq[b,j,k]); d_q2 = relu(A @ q2_w^T + q2_b). M=15872,N=300,K=600.
__global__ void gemm_pairs(const float* __restrict__ W, const float* __restrict__ bias)
{
    __shared__ float As[16][65];
    __shared__ float Ws[16][65];
    int m0 = blockIdx.y * 64, n0 = blockIdx.x * 64;
    int tid = threadIdx.x;
    int ty = tid / 16, tx = tid % 16;
    float acc[4][4];
    #pragma unroll
    for (int i = 0; i < 4; i++)
        #pragma unroll
        for (int j = 0; j < 4; j++) acc[i][j] = 0.f;

    for (int kk = 0; kk < Q1S; kk += 16) {
        #pragma unroll
        for (int r = 0; r < 4; r++) {
            int idx = tid + r * 256;
            int row = idx >> 4, col = idx & 15;
            int gk = kk + col;
            int m = m0 + row;
            int b = m / PP, p = m - b * PP;
            float av = 0.f;
            if (gk < Q1S) {
                int pi = d_pi[p], pj = d_pj[p];
                av = fmaxf(d_Aq[(size_t)(b * 32 + pi) * Q1S + gk] +
                           d_Bq[(size_t)(b * 32 + pj) * Q1S + gk], 0.f);
            }
            As[col][row] = av;
            int gn = n0 + row;
            Ws[col][row] = (gn < QS && gk < Q1S) ? W[gn * Q1S + gk] : 0.f;
        }
        __syncthreads();
        #pragma unroll
        for (int k = 0; k < 16; k++) {
            float a[4], b[4];
            #pragma unroll
            for (int i = 0; i < 4; i++) a[i] = As[k][ty * 4 + i];
            #pragma unroll
            for (int j = 0; j < 4; j++) b[j] = Ws[k][tx * 4 + j];
            #pragma unroll
            for (int i = 0; i < 4; i++)
                #pragma unroll
                for (int j = 0; j < 4; j++) acc[i][j] = fmaf(a[i], b[j], acc[i][j]);
        }
        __syncthreads();
    }
    #pragma unroll
    for (int i = 0; i < 4; i++) {
        int gm = m0 + ty * 4 + i;
        #pragma unroll
        for (int j = 0; j < 4; j++) {
            int gn = n0 + tx * 4 + j;
            if (gn < QS)
                d_q2[(size_t)gm * QS + gn] = fmaxf(acc[i][j] + bias[gn], 0.f);
        }
    }
}

// ---------------- LSTM gate/state update ----------------
__global__ void lstm_combine(int t) {
    int idx = blockIdx.x * blockDim.x + threadIdx.x;
    if (idx >= BB * HH) return;
    int b = idx / HH, j = idx - b * HH;
    const float* xpt = d_xp + (size_t)(t * 32 + b) * G4;
    float g[4];
    #pragma unroll
    for (int gg = 0; gg < 4; gg++) {
        int r = gg * HH + j;
        float v = xpt[r];
        v += d_gpart[0][b * G4 + r] + d_gpart[1][b * G4 + r] +
             d_gpart[2][b * G4 + r] + d_gpart[3][b * G4 + r];
        g[gg] = v;
    }
    float ci = 1.f / (1.f + expf(-g[0]));
    float cf = 1.f / (1.f + expf(-g[1]));
    float cg = tanhf(g[2]);
    float co = 1.f / (1.f + expf(-g[3]));
    float cn = cf * d_c[idx] + ci * cg;
    d_c[idx] = cn;
    d_h[(t + 1) & 1][idx] = co * tanhf(cn);
}

// ---------------- tail: e3 + e4 fused ----------------
__global__ void k_tail(const float* __restrict__ e3w, const float* __restrict__ e3b,
                       const float* __restrict__ e4w, const float* __restrict__ e4b,
                       float* __restrict__ out)
{
    __shared__ float s2[64][101];
    __shared__ float sw[10][100];
    __shared__ float sb[10], s4[10];
    __shared__ float s4b;
    int m0 = blockIdx.x * 64;
    int tid = threadIdx.x;  // 64
    for (int l = 0; l < 100; l++) {
        int idx = tid + l * 64;
        s2[idx / 100][idx % 100] = d_e2buf[(size_t)m0 * EV2S + idx];
    }
    if (tid < 10) { sb[tid] = e3b[tid]; s4[tid] = e4w[tid]; }
    if (tid == 0) s4b = e4b[0];
    for (int l = tid; l < 1000; l += 64) sw[l / 100][l % 100] = e3w[l];
    __syncthreads();
    float acc = s4b;
    #pragma unroll
    for (int g = 0; g < 10; g++) {
        float a = sb[g];
        #pragma unroll 4
        for (int k = 0; k < 100; k++) a = fmaf(s2[tid][k], sw[g][k], a);
        acc = fmaf(fmaxf(a, 0.f), s4[g], acc);
    }
    out[m0 + tid] = fmaxf(acc, 0.f);
}

// ---------------- launch ----------------
extern "C" void kernel_launch(void* const* d_in, const int* in_sizes, int n_in,
                              void* d_out, int out_size)
{
    const float* x    = (const float*)d_in[0];
    const float* w_ih = (const float*)d_in[1];
    const float* w_hh = (const float*)d_in[2];
    const float* b_ih = (const float*)d_in[3];
    const float* b_hh = (const float*)d_in[4];
    const float* q1_w = (const float*)d_in[5];
    const float* q1_b = (const float*)d_in[6];
    const float* q2_w = (const float*)d_in[7];
    const float* q2_b = (const float*)d_in[8];
    const float* e1_w = (const float*)d_in[9];
    const float* e1_b = (const float*)d_in[10];
    const float* e2_w = (const float*)d_in[11];
    const float* e2_b = (const float*)d_in[12];
    const float* e3_w = (const float*)d_in[13];
    const float* e3_b = (const float*)d_in[14];
    const float* e4_w = (const float*)d_in[15];
    const float* e4_b = (const float*)d_in[16];
    float* out = (float*)d_out;

    float *pS, *pXp, *pH0, *pH1, *pGp, *pQb, *pAq, *pBq, *pPt, *pQ2, *pE1, *pE2;
    cudaGetSymbolAddress((void**)&pS,  d_S);
    cudaGetSymbolAddress((void**)&pXp, d_xp);
    cudaGetSymbolAddress((void**)&pH0, d_h);           // d_h[0]
    pH1 = pH0 + BB * HH;
    cudaGetSymbolAddress((void**)&pGp, d_gpart);
    cudaGetSymbolAddress((void**)&pQb, d_q1beff);
    cudaGetSymbolAddress((void**)&pAq, d_Aq);
    cudaGetSymbolAddress((void**)&pBq, d_Bq);
    cudaGetSymbolAddress((void**)&pPt, d_pt);
    cudaGetSymbolAddress((void**)&pQ2, d_q2);
    cudaGetSymbolAddress((void**)&pE1, d_e1buf);
    cudaGetSymbolAddress((void**)&pE2, d_e2buf);

    // 1. sort parts
    k_sort<<<32, 256>>>(x);
    // 2. pair indices + effective q1 bias + zero state
    k_init<<<(PP + Q1S + 3 * BB * HH + 255) / 256, 256>>>(q1_w, q1_b);
    // 3. input projections for all 32 steps: xp = S @ w_ih^T + b_ih + b_hh
    gemm_nt<64><<<dim3((G4 + 63) / 64, MNB / 64, 1), 256>>>(
        pS, EE, w_ih, EE, b_ih, b_hh, nullptr, 1, pXp, MNB, G4, EE, 0);
    // 4. factored q1 halves (pairs never materialized)
    gemm_nt<64><<<dim3((Q1S + 63) / 64, MNB / 64, 1), 256>>>(
        x, EE, q1_w, 2 * EE, pQb, nullptr, nullptr, 1, pAq, MNB, Q1S, EE, 0);
    gemm_nt<64><<<dim3((Q1S + 63) / 64, MNB / 64, 1), 256>>>(
        x, EE, q1_w + EE, 2 * EE, nullptr, nullptr, nullptr, 1, pBq, MNB, Q1S, EE, 0);
    // 5. LSTM recurrence: 32 sequential steps, each = K-split GEMM + gate update
    for (int t = 0; t < 32; t++) {
        const float* hprev = (t & 1) ? pH1 : pH0;
        gemm_nt<32><<<dim3((G4 + 63) / 64, 1, 4), 128>>>(
            hprev, HH, w_hh, HH, nullptr, nullptr, nullptr, 1, pGp, BB, G4, HH, 0);
        lstm_combine<<<(BB * HH + 255) / 256, 256>>>(t);
    }
    // 6. plan term: pt = plan @ e1_w[:, :H]^T + e1_b   (plan lives in d_h[0] after t=31)
    gemm_nt<32><<<dim3((EV1S + 63) / 64, 1, 1), 128>>>(
        pH0, HH, e1_w, HH + QS, e1_b, nullptr, nullptr, 1, pPt, BB, EV1S, HH, 0);
    // 7. q2 with fused pair construction
    gemm_pairs<<<dim3((QS + 63) / 64, MPAIR / 64, 1), 256>>>(q2_w, q2_b);
    // 8. e1 (q side) + broadcast plan term, relu
    gemm_nt<64><<<dim3((EV1S + 63) / 64, MPAIR / 64, 1), 256>>>(
        pQ2, QS, e1_w + HH, HH + QS, nullptr, nullptr, pPt, PP, pE1, MPAIR, EV1S, QS, 1);
    // 9. e2
    gemm_nt<64><<<dim3((EV2S + 63) / 64, MPAIR / 64, 1), 256>>>(
        pE1, EV1S, e2_w, EV1S, e2_b, nullptr, nullptr, 1, pE2, MPAIR, EV2S, EV1S, 1);
    // 10. e3+e4 fused tail
    k_tail<<<MPAIR / 64, 64>>>(e3_w, e3_b, e4_w, e4_b, out);
}

// round 3
// speedup vs baseline: 1.3858x; 1.3858x over previous
#include <cuda_runtime.h>
#include <math.h>

typedef unsigned long long ull;

// ---------------- problem constants ----------------
#define BB 32
#define NN 32
#define EE 256
#define HH 1500
#define G4 6000
#define PP 496
#define Q1S 600
#define QS 300
#define EV1S 1000
#define EV2S 100
#define MPAIR (BB*PP)   // 15872
#define MNB (NN*BB)     // 1024
#define NZ 5            // K-splits for LSTM gemm (1500/5 = 300, %4==0)

// ---------------- device scratch ----------------
__device__ float d_S[MNB*EE];
__device__ float d_xp[(size_t)MNB*G4];
__device__ float d_h[2][BB*HH];
__device__ float d_c[BB*HH];
__device__ float d_gpart[NZ][BB*G4];
__device__ float d_q1beff[Q1S];
__device__ int   d_pi[PP], d_pj[PP];
__device__ float d_Aq[MNB*Q1S];
__device__ float d_Bq[MNB*Q1S];
__device__ float d_pt[BB*EV1S];
__device__ float d_q2[(size_t)MPAIR*QS];
__device__ float d_e1buf[(size_t)MPAIR*EV1S];
__device__ float d_e2buf[MPAIR*EV2S];

// ---------------- f32x2 helpers (Blackwell packed fp32) ----------------
__device__ __forceinline__ ull fma2(ull a, ull b, ull c) {
    ull d; asm("fma.rn.f32x2 %0, %1, %2, %3;" : "=l"(d) : "l"(a), "l"(b), "l"(c)); return d;
}
__device__ __forceinline__ ull dup2(float x) {
    ull d; unsigned u = __float_as_uint(x);
    asm("mov.b64 %0, {%1, %1};" : "=l"(d) : "r"(u)); return d;
}
__device__ __forceinline__ float2 unpk(ull v) {
    float2 r; asm("mov.b64 {%0, %1}, %2;" : "=f"(r.x), "=f"(r.y) : "l"(v)); return r;
}

// ---------------- sort: per (b,e) sort 32 values along parts ----------------
__global__ void k_sort(const float* __restrict__ x) {
    int tid = blockIdx.x * blockDim.x + threadIdx.x;   // 0..8191
    int b = tid >> 8, e = tid & 255;
    float v[32];
    #pragma unroll
    for (int t = 0; t < 32; t++) v[t] = x[(b * 32 + t) * EE + e];
    for (int a = 1; a < 32; a++) {
        float key = v[a];
        int c = a - 1;
        while (c >= 0 && v[c] > key) { v[c + 1] = v[c]; c--; }
        v[c + 1] = key;
    }
    #pragma unroll
    for (int t = 0; t < 32; t++) d_S[(t * 32 + b) * EE + e] = v[t];
}

// ---------------- init ----------------
__global__ void k_init(const float* __restrict__ q1_w, const float* __restrict__ q1_b) {
    int idx = blockIdx.x * blockDim.x + threadIdx.x;
    if (idx < PP) {
        int p = idx, i = 0, cnt = 31;
        while (p >= cnt) { p -= cnt; i++; cnt--; }
        d_pi[idx] = i; d_pj[idx] = i + 1 + p;
    } else if (idx < PP + Q1S) {
        int o = idx - PP;
        float s = q1_b[o];
        for (int d = 1; d < 2 * EE; d += 2) s += q1_w[o * (2 * EE) + d];
        d_q1beff[o] = s;
    } else {
        int z = idx - (PP + Q1S);
        if (z < BB * HH)           d_h[0][z] = 0.f;
        else if (z < 2 * BB * HH)  d_h[1][z - BB * HH] = 0.f;
        else if (z < 3 * BB * HH)  d_c[z - 2 * BB * HH] = 0.f;
    }
}

// ---------------- gemm128: C[M,Nn] = act(A[M,K] @ W[Nn,K]^T + biases) ----------------
// Requires M % 128 == 0, K % 4 == 0. 256 threads; tile 128x64; thread = 8(M)x4(N).
__global__ void gemm128(const float* __restrict__ A, int lda,
                        const float* __restrict__ W, int ldw,
                        const float* __restrict__ bias0, const float* __restrict__ bias1,
                        const float* __restrict__ rowterm, int rowdiv,
                        float* __restrict__ C, int M, int Nn, int K, int relu)
{
    __shared__ float As[16][132];
    __shared__ float Ws[16][68];
    int m0 = blockIdx.y * 128, n0 = blockIdx.x * 64;
    int tid = threadIdx.x;
    int tx = tid & 15, ty = tid >> 4;

    // hoisted A-load addressing (2 float4 per thread)
    int arow0 = (tid * 2) >> 2,       acv0 = (tid * 2) & 3;
    int arow1 = (tid * 2 + 1) >> 2,   acv1 = (tid * 2 + 1) & 3;
    const float* ap0 = A + (size_t)(m0 + arow0) * lda;
    const float* ap1 = A + (size_t)(m0 + arow1) * lda;
    // W load (1 float4 per thread)
    int wrow = tid >> 2, wcv = tid & 3;
    int gn_w = n0 + wrow;
    const float* wp = W + (size_t)(gn_w < Nn ? gn_w : 0) * ldw;
    bool wok = (gn_w < Nn);

    ull acc[4][4];
    #pragma unroll
    for (int i = 0; i < 4; i++)
        #pragma unroll
        for (int j = 0; j < 4; j++) acc[i][j] = dup2(0.f);

    for (int kk = 0; kk < K; kk += 16) {
        {
            int gk = kk + acv0 * 4;
            float4 v = (gk < K) ? *(const float4*)&ap0[gk] : make_float4(0,0,0,0);
            As[acv0*4+0][arow0] = v.x; As[acv0*4+1][arow0] = v.y;
            As[acv0*4+2][arow0] = v.z; As[acv0*4+3][arow0] = v.w;
            gk = kk + acv1 * 4;
            v = (gk < K) ? *(const float4*)&ap1[gk] : make_float4(0,0,0,0);
            As[acv1*4+0][arow1] = v.x; As[acv1*4+1][arow1] = v.y;
            As[acv1*4+2][arow1] = v.z; As[acv1*4+3][arow1] = v.w;
        }
        {
            int gk = kk + wcv * 4;
            float4 v = (wok && gk < K) ? *(const float4*)&wp[gk] : make_float4(0,0,0,0);
            Ws[wcv*4+0][wrow] = v.x; Ws[wcv*4+1][wrow] = v.y;
            Ws[wcv*4+2][wrow] = v.z; Ws[wcv*4+3][wrow] = v.w;
        }
        __syncthreads();
        #pragma unroll
        for (int k = 0; k < 16; k++) {
            const ull* a64 = (const ull*)&As[k][ty * 8];
            ull a0 = a64[0], a1 = a64[1], a2 = a64[2], a3 = a64[3];
            float4 b4 = *(const float4*)&Ws[k][tx * 4];
            ull b0 = dup2(b4.x), b1 = dup2(b4.y), b2 = dup2(b4.z), b3 = dup2(b4.w);
            acc[0][0]=fma2(a0,b0,acc[0][0]); acc[0][1]=fma2(a0,b1,acc[0][1]);
            acc[0][2]=fma2(a0,b2,acc[0][2]); acc[0][3]=fma2(a0,b3,acc[0][3]);
            acc[1][0]=fma2(a1,b0,acc[1][0]); acc[1][1]=fma2(a1,b1,acc[1][1]);
            acc[1][2]=fma2(a1,b2,acc[1][2]); acc[1][3]=fma2(a1,b3,acc[1][3]);
            acc[2][0]=fma2(a2,b0,acc[2][0]); acc[2][1]=fma2(a2,b1,acc[2][1]);
            acc[2][2]=fma2(a2,b2,acc[2][2]); acc[2][3]=fma2(a2,b3,acc[2][3]);
            acc[3][0]=fma2(a3,b0,acc[3][0]); acc[3][1]=fma2(a3,b1,acc[3][1]);
            acc[3][2]=fma2(a3,b2,acc[3][2]); acc[3][3]=fma2(a3,b3,acc[3][3]);
        }
        __syncthreads();
    }

    #pragma unroll
    for (int i = 0; i < 4; i++) {
        int gm = m0 + ty * 8 + i * 2;
        #pragma unroll
        for (int j = 0; j < 4; j++) {
            int gn = n0 + tx * 4 + j;
            if (gn >= Nn) continue;
            float2 v = unpk(acc[i][j]);
            float add = 0.f;
            if (bias0) add += bias0[gn];
            if (bias1) add += bias1[gn];
            float v0 = v.x + add, v1 = v.y + add;
            if (rowterm) {
                v0 += rowterm[(size_t)(gm / rowdiv) * Nn + gn];
                v1 += rowterm[(size_t)((gm + 1) / rowdiv) * Nn + gn];
            }
            if (relu) { v0 = fmaxf(v0, 0.f); v1 = fmaxf(v1, 0.f); }
            C[(size_t)gm * Nn + gn] = v0;
            C[(size_t)(gm + 1) * Nn + gn] = v1;
        }
    }
}

// ---------------- gemm_pairs128: fused pair construction, then GEMM ----------------
// A[m,k] = relu(Aq[b,pi,k] + Bq[b,pj,k]); d_q2 = relu(A @ q2_w^T + q2_b).
__global__ void gemm_pairs128(const float* __restrict__ W, const float* __restrict__ bias)
{
    __shared__ float As[16][132];
    __shared__ float Ws[16][68];
    int m0 = blockIdx.y * 128, n0 = blockIdx.x * 64;
    int tid = threadIdx.x;
    int tx = tid & 15, ty = tid >> 4;

    // hoisted pair addressing (2 rows per thread)
    const float *pa[2], *pb[2];
    int acv[2], arow[2];
    #pragma unroll
    for (int r = 0; r < 2; r++) {
        int idx = tid * 2 + r;
        arow[r] = idx >> 2; acv[r] = idx & 3;
        int m = m0 + arow[r];
        int b = m / PP, p = m - b * PP;
        pa[r] = d_Aq + (size_t)(b * 32 + d_pi[p]) * Q1S;
        pb[r] = d_Bq + (size_t)(b * 32 + d_pj[p]) * Q1S;
    }
    int wrow = tid >> 2, wcv = tid & 3;
    int gn_w = n0 + wrow;
    const float* wp = W + (size_t)(gn_w < QS ? gn_w : 0) * Q1S;
    bool wok = (gn_w < QS);

    ull acc[4][4];
    #pragma unroll
    for (int i = 0; i < 4; i++)
        #pragma unroll
        for (int j = 0; j < 4; j++) acc[i][j] = dup2(0.f);

    for (int kk = 0; kk < Q1S; kk += 16) {
        #pragma unroll
        for (int r = 0; r < 2; r++) {
            int gk = kk + acv[r] * 4;
            float4 v = make_float4(0,0,0,0);
            if (gk < Q1S) {
                float4 a = *(const float4*)&pa[r][gk];
                float4 b = *(const float4*)&pb[r][gk];
                v.x = fmaxf(a.x + b.x, 0.f); v.y = fmaxf(a.y + b.y, 0.f);
                v.z = fmaxf(a.z + b.z, 0.f); v.w = fmaxf(a.w + b.w, 0.f);
            }
            As[acv[r]*4+0][arow[r]] = v.x; As[acv[r]*4+1][arow[r]] = v.y;
            As[acv[r]*4+2][arow[r]] = v.z; As[acv[r]*4+3][arow[r]] = v.w;
        }
        {
            int gk = kk + wcv * 4;
            float4 v = (wok && gk < Q1S) ? *(const float4*)&wp[gk] : make_float4(0,0,0,0);
            Ws[wcv*4+0][wrow] = v.x; Ws[wcv*4+1][wrow] = v.y;
            Ws[wcv*4+2][wrow] = v.z; Ws[wcv*4+3][wrow] = v.w;
        }
        __syncthreads();
        #pragma unroll
        for (int k = 0; k < 16; k++) {
            const ull* a64 = (const ull*)&As[k][ty * 8];
            ull a0 = a64[0], a1 = a64[1], a2 = a64[2], a3 = a64[3];
            float4 b4 = *(const float4*)&Ws[k][tx * 4];
            ull b0 = dup2(b4.x), b1 = dup2(b4.y), b2 = dup2(b4.z), b3 = dup2(b4.w);
            acc[0][0]=fma2(a0,b0,acc[0][0]); acc[0][1]=fma2(a0,b1,acc[0][1]);
            acc[0][2]=fma2(a0,b2,acc[0][2]); acc[0][3]=fma2(a0,b3,acc[0][3]);
            acc[1][0]=fma2(a1,b0,acc[1][0]); acc[1][1]=fma2(a1,b1,acc[1][1]);
            acc[1][2]=fma2(a1,b2,acc[1][2]); acc[1][3]=fma2(a1,b3,acc[1][3]);
            acc[2][0]=fma2(a2,b0,acc[2][0]); acc[2][1]=fma2(a2,b1,acc[2][1]);
            acc[2][2]=fma2(a2,b2,acc[2][2]); acc[2][3]=fma2(a2,b3,acc[2][3]);
            acc[3][0]=fma2(a3,b0,acc[3][0]); acc[3][1]=fma2(a3,b1,acc[3][1]);
            acc[3][2]=fma2(a3,b2,acc[3][2]); acc[3][3]=fma2(a3,b3,acc[3][3]);
        }
        __syncthreads();
    }

    #pragma unroll
    for (int i = 0; i < 4; i++) {
        int gm = m0 + ty * 8 + i * 2;
        #pragma unroll
        for (int j = 0; j < 4; j++) {
            int gn = n0 + tx * 4 + j;
            if (gn >= QS) continue;
            float2 v = unpk(acc[i][j]);
            d_q2[(size_t)gm * QS + gn]       = fmaxf(v.x + bias[gn], 0.f);
            d_q2[(size_t)(gm + 1) * QS + gn] = fmaxf(v.y + bias[gn], 0.f);
        }
    }
}

// ---------------- gemm_small: M=32 tile; C = A[32,K] @ W[Nn,K]^T (+bias if z==1) ----
// 128 threads; tile 32x128; thread = 4(M) x 8(N as 4 f32x2 pairs).
// gridDim.z splits K (chunk = K/z, must be %4==0); partials at C + z*32*Nn.
__global__ void gemm_small(const float* __restrict__ A, int lda,
                           const float* __restrict__ W, int ldw,
                           const float* __restrict__ bias,
                           float* __restrict__ C, int Nn, int K)
{
    __shared__ float As[16][36];
    __shared__ float Ws[16][136];
    int kchunk = K / gridDim.z;
    int k0 = blockIdx.z * kchunk, k1 = k0 + kchunk;
    float* Cz = C + (size_t)blockIdx.z * 32 * Nn;
    int n0 = blockIdx.x * 128;
    int tid = threadIdx.x;
    int tx = tid & 15, ty = tid >> 4;   // ty 0..7 -> 4 M rows each; tx -> 8 N cols

    int arow = tid >> 2, acv = tid & 3;          // A: 32 rows x 4 f4
    const float* ap = A + (size_t)arow * lda;
    int wrow4 = tid >> 2, wcv = tid & 3;         // W: 4 f4 per thread over 128 rows
    ull acc[4][4];
    #pragma unroll
    for (int i = 0; i < 4; i++)
        #pragma unroll
        for (int j = 0; j < 4; j++) acc[i][j] = dup2(0.f);

    for (int kk = k0; kk < k1; kk += 16) {
        {
            int gk = kk + acv * 4;
            float4 v = (gk < k1) ? *(const float4*)&ap[gk] : make_float4(0,0,0,0);
            As[acv*4+0][arow] = v.x; As[acv*4+1][arow] = v.y;
            As[acv*4+2][arow] = v.z; As[acv*4+3][arow] = v.w;
        }
        #pragma unroll
        for (int r = 0; r < 4; r++) {
            int row = wrow4 + r * 32;
            int gn = n0 + row, gk = kk + wcv * 4;
            float4 v = (gn < Nn && gk < k1) ?
                *(const float4*)&W[(size_t)gn * ldw + gk] : make_float4(0,0,0,0);
            Ws[wcv*4+0][row] = v.x; Ws[wcv*4+1][row] = v.y;
            Ws[wcv*4+2][row] = v.z; Ws[wcv*4+3][row] = v.w;
        }
        __syncthreads();
        #pragma unroll
        for (int k = 0; k < 16; k++) {
            float4 a4 = *(const float4*)&As[k][ty * 4];
            ull a0 = dup2(a4.x), a1 = dup2(a4.y), a2 = dup2(a4.z), a3 = dup2(a4.w);
            const ull* b64 = (const ull*)&Ws[k][tx * 8];
            ull b0 = b64[0], b1 = b64[1], b2 = b64[2], b3 = b64[3];
            acc[0][0]=fma2(a0,b0,acc[0][0]); acc[0][1]=fma2(a0,b1,acc[0][1]);
            acc[0][2]=fma2(a0,b2,acc[0][2]); acc[0][3]=fma2(a0,b3,acc[0][3]);
            acc[1][0]=fma2(a1,b0,acc[1][0]); acc[1][1]=fma2(a1,b1,acc[1][1]);
            acc[1][2]=fma2(a1,b2,acc[1][2]); acc[1][3]=fma2(a1,b3,acc[1][3]);
            acc[2][0]=fma2(a2,b0,acc[2][0]); acc[2][1]=fma2(a2,b1,acc[2][1]);
            acc[2][2]=fma2(a2,b2,acc[2][2]); acc[2][3]=fma2(a2,b3,acc[2][3]);
            acc[3][0]=fma2(a3,b0,acc[3][0]); acc[3][1]=fma2(a3,b1,acc[3][1]);
            acc[3][2]=fma2(a3,b2,acc[3][2]); acc[3][3]=fma2(a3,b3,acc[3][3]);
        }
        __syncthreads();
    }

    #pragma unroll
    for (int i = 0; i < 4; i++) {
        int gm = ty * 4 + i;
        #pragma unroll
        for (int j = 0; j < 4; j++) {
            int gn = n0 + tx * 8 + j * 2;
            if (gn >= Nn) continue;
            float2 v = unpk(acc[i][j]);
            if (bias) { v.x += bias[gn]; if (gn + 1 < Nn) v.y += bias[gn + 1]; }
            Cz[(size_t)gm * Nn + gn] = v.x;
            if (gn + 1 < Nn) Cz[(size_t)gm * Nn + gn + 1] = v.y;
        }
    }
}

// ---------------- LSTM gate/state update (float2 vectorized) ----------------
__global__ void lstm_combine(int t) {
    int idx = blockIdx.x * blockDim.x + threadIdx.x;   // < BB*HH/2
    if (idx >= BB * HH / 2) return;
    int b = idx / (HH / 2), j = (idx - b * (HH / 2)) * 2;
    const float* xpt = d_xp + (size_t)(t * 32 + b) * G4;
    float2 g[4];
    #pragma unroll
    for (int gg = 0; gg < 4; gg++) {
        int r = gg * HH + j;
        float2 v = *(const float2*)&xpt[r];
        #pragma unroll
        for (int z = 0; z < NZ; z++) {
            float2 p = *(const float2*)&d_gpart[z][b * G4 + r];
            v.x += p.x; v.y += p.y;
        }
        g[gg] = v;
    }
    float2 cold = *(const float2*)&d_c[b * HH + j];
    float ci0 = 1.f/(1.f+expf(-g[0].x)), ci1 = 1.f/(1.f+expf(-g[0].y));
    float cf0 = 1.f/(1.f+expf(-g[1].x)), cf1 = 1.f/(1.f+expf(-g[1].y));
    float cg0 = tanhf(g[2].x),           cg1 = tanhf(g[2].y);
    float co0 = 1.f/(1.f+expf(-g[3].x)), co1 = 1.f/(1.f+expf(-g[3].y));
    float2 cn = make_float2(cf0 * cold.x + ci0 * cg0, cf1 * cold.y + ci1 * cg1);
    *(float2*)&d_c[b * HH + j] = cn;
    float2 hn = make_float2(co0 * tanhf(cn.x), co1 * tanhf(cn.y));
    *(float2*)&d_h[(t + 1) & 1][b * HH + j] = hn;
}

// ---------------- tail: e3 + e4 fused ----------------
__global__ void k_tail(const float* __restrict__ e3w, const float* __restrict__ e3b,
                       const float* __restrict__ e4w, const float* __restrict__ e4b,
                       float* __restrict__ out)
{
    __shared__ float s2[64][101];
    __shared__ float sw[10][100];
    __shared__ float sb[10], s4[10];
    __shared__ float s4b;
    int m0 = blockIdx.x * 64;
    int tid = threadIdx.x;  // 64
    for (int l = 0; l < 100; l++) {
        int idx = tid + l * 64;
        s2[idx / 100][idx % 100] = d_e2buf[(size_t)m0 * EV2S + idx];
    }
    if (tid < 10) { sb[tid] = e3b[tid]; s4[tid] = e4w[tid]; }
    if (tid == 0) s4b = e4b[0];
    for (int l = tid; l < 1000; l += 64) sw[l / 100][l % 100] = e3w[l];
    __syncthreads();
    float acc = s4b;
    #pragma unroll
    for (int g = 0; g < 10; g++) {
        float a = sb[g];
        #pragma unroll 4
        for (int k = 0; k < 100; k++) a = fmaf(s2[tid][k], sw[g][k], a);
        acc = fmaf(fmaxf(a, 0.f), s4[g], acc);
    }
    out[m0 + tid] = fmaxf(acc, 0.f);
}

// ---------------- launch ----------------
extern "C" void kernel_launch(void* const* d_in, const int* in_sizes, int n_in,
                              void* d_out, int out_size)
{
    const float* x    = (const float*)d_in[0];
    const float* w_ih = (const float*)d_in[1];
    const float* w_hh = (const float*)d_in[2];
    const float* b_ih = (const float*)d_in[3];
    const float* b_hh = (const float*)d_in[4];
    const float* q1_w = (const float*)d_in[5];
    const float* q1_b = (const float*)d_in[6];
    const float* q2_w = (const float*)d_in[7];
    const float* q2_b = (const float*)d_in[8];
    const float* e1_w = (const float*)d_in[9];
    const float* e1_b = (const float*)d_in[10];
    const float* e2_w = (const float*)d_in[11];
    const float* e2_b = (const float*)d_in[12];
    const float* e3_w = (const float*)d_in[13];
    const float* e3_b = (const float*)d_in[14];
    const float* e4_w = (const float*)d_in[15];
    const float* e4_b = (const float*)d_in[16];
    float* out = (float*)d_out;

    float *pS, *pXp, *pH0, *pH1, *pGp, *pQb, *pAq, *pBq, *pPt, *pQ2, *pE1, *pE2;
    cudaGetSymbolAddress((void**)&pS,  d_S);
    cudaGetSymbolAddress((void**)&pXp, d_xp);
    cudaGetSymbolAddress((void**)&pH0, d_h);
    pH1 = pH0 + BB * HH;
    cudaGetSymbolAddress((void**)&pGp, d_gpart);
    cudaGetSymbolAddress((void**)&pQb, d_q1beff);
    cudaGetSymbolAddress((void**)&pAq, d_Aq);
    cudaGetSymbolAddress((void**)&pBq, d_Bq);
    cudaGetSymbolAddress((void**)&pPt, d_pt);
    cudaGetSymbolAddress((void**)&pQ2, d_q2);
    cudaGetSymbolAddress((void**)&pE1, d_e1buf);
    cudaGetSymbolAddress((void**)&pE2, d_e2buf);

    // 1. sort parts
    k_sort<<<32, 256>>>(x);
    // 2. pair indices + effective q1 bias + zero state
    k_init<<<(PP + Q1S + 3 * BB * HH + 255) / 256, 256>>>(q1_w, q1_b);
    // 3. input projections: xp = S @ w_ih^T + b_ih + b_hh  [1024 x 6000 x 256]
    gemm128<<<dim3((G4 + 63) / 64, MNB / 128), 256>>>(
        pS, EE, w_ih, EE, b_ih, b_hh, nullptr, 1, pXp, MNB, G4, EE, 0);
    // 4. factored q1 halves
    gemm128<<<dim3((Q1S + 63) / 64, MNB / 128), 256>>>(
        x, EE, q1_w, 2 * EE, pQb, nullptr, nullptr, 1, pAq, MNB, Q1S, EE, 0);
    gemm128<<<dim3((Q1S + 63) / 64, MNB / 128), 256>>>(
        x, EE, q1_w + EE, 2 * EE, nullptr, nullptr, nullptr, 1, pBq, MNB, Q1S, EE, 0);
    // 5. LSTM recurrence
    for (int t = 0; t < 32; t++) {
        const float* hprev = (t & 1) ? pH1 : pH0;
        gemm_small<<<dim3((G4 + 127) / 128, 1, NZ), 128>>>(
            hprev, HH, w_hh, HH, nullptr, pGp, G4, HH);
        lstm_combine<<<(BB * HH / 2 + 255) / 256, 256>>>(t);
    }
    // 6. plan term: pt = plan @ e1_w[:, :H]^T + e1_b
    gemm_small<<<dim3((EV1S + 127) / 128, 1, 1), 128>>>(
        pH0, HH, e1_w, HH + QS, e1_b, pPt, EV1S, HH);
    // 7. q2 with fused pair construction  [15872 x 300 x 600]
    gemm_pairs128<<<dim3((QS + 63) / 64, MPAIR / 128), 256>>>(q2_w, q2_b);
    // 8. e1 (q side) + broadcast plan term  [15872 x 1000 x 300]
    gemm128<<<dim3((EV1S + 63) / 64, MPAIR / 128), 256>>>(
        pQ2, QS, e1_w + HH, HH + QS, nullptr, nullptr, pPt, PP, pE1, MPAIR, EV1S, QS, 1);
    // 9. e2  [15872 x 100 x 1000]
    gemm128<<<dim3((EV2S + 63) / 64, MPAIR / 128), 256>>>(
        pE1, EV1S, e2_w, EV1S, e2_b, nullptr, nullptr, 1, pE2, MPAIR, EV2S, EV1S, 1);
    // 10. e3+e4 fused tail
    k_tail<<<MPAIR / 64, 64>>>(e3_w, e3_b, e4_w, e4_b, out);
}

// round 5
// speedup vs baseline: 2.7175x; 1.9610x over previous
#include <cuda_runtime.h>
#include <cuda_bf16.h>
#include <math.h>
#include <stdint.h>

// ---------------- problem constants ----------------
#define BB 32
#define NN 32
#define EE 256
#define HH 1500
#define G4 6000
#define PP 496
#define Q1S 600
#define QS 300
#define EV1S 1000
#define EV2S 100
#define MPAIR (BB*PP)   // 15872
#define MNB (NN*BB)     // 1024
#define G4P 6144        // 24*256 (padded M for whh)
#define KHP 1536        // padded K stride for whh
#define PTP 1024        // padded M for pt partials

// ---------------- device scratch ----------------
__device__ float d_S[MNB*EE];                      // sorted seq rows (t*32+b)
__device__ float d_xp[(size_t)G4*MNB];             // [r][t*32+b]
__device__ float d_h[2][BB*HH];                    // [b][j]
__device__ float d_cT[BB*HH];                      // [j*32+b]
__device__ float d_gpart4[4][G4P*BB];              // K-split partials [r][b]
__device__ float d_pt4[4][PTP*BB];                 // pt partials [n][b]
__device__ float d_ptT[EV1S*BB];                   // combined [n][b]
__device__ float d_q1beff[Q1S];
__device__ int   d_pi[PP], d_pj[PP];
__device__ float d_Aq[MNB*Q1S];
__device__ float d_Bq[MNB*Q1S];
__device__ float d_q2[(size_t)MPAIR*QS];
__device__ float d_e1buf[(size_t)MPAIR*EV1S];
__device__ float d_e2buf[MPAIR*EV2S];
__device__ __nv_bfloat16 d_whh_hi[(size_t)G4P*KHP];
__device__ __nv_bfloat16 d_whh_lo[(size_t)G4P*KHP];

// ---------------- helpers ----------------
__device__ __forceinline__ uint32_t smem_u32(const void* p) {
    uint32_t a;
    asm("{ .reg .u64 t; cvta.to.shared.u64 t, %1; cvt.u32.u64 %0, t; }" : "=r"(a) : "l"(p));
    return a;
}
__device__ __forceinline__ void ldsm4(uint32_t* r, uint32_t addr) {
    asm volatile("ldmatrix.sync.aligned.m8n8.x4.shared.b16 {%0,%1,%2,%3}, [%4];"
        : "=r"(r[0]), "=r"(r[1]), "=r"(r[2]), "=r"(r[3]) : "r"(addr));
}
__device__ __forceinline__ void ldsm2(uint32_t* r, uint32_t addr) {
    asm volatile("ldmatrix.sync.aligned.m8n8.x2.shared.b16 {%0,%1}, [%2];"
        : "=r"(r[0]), "=r"(r[1]) : "r"(addr));
}
__device__ __forceinline__ void mma16816(float* c, const uint32_t* a, const uint32_t* b) {
    asm volatile("mma.sync.aligned.m16n8k16.row.col.f32.bf16.bf16.f32 "
        "{%0,%1,%2,%3}, {%4,%5,%6,%7}, {%8,%9}, {%0,%1,%2,%3};"
        : "+f"(c[0]), "+f"(c[1]), "+f"(c[2]), "+f"(c[3])
        : "r"(a[0]), "r"(a[1]), "r"(a[2]), "r"(a[3]), "r"(b[0]), "r"(b[1]));
}
__device__ __forceinline__ void bsplit(float v, unsigned& h, unsigned& l) {
    __nv_bfloat16 bh = __float2bfloat16_rn(v);
    float r = v - __bfloat162float(bh);
    __nv_bfloat16 bl = __float2bfloat16_rn(r);
    h = (unsigned)__bfloat16_as_ushort(bh);
    l = (unsigned)__bfloat16_as_ushort(bl);
}
__device__ __forceinline__ void conv8(float4 a, float4 b, uint4& H, uint4& L) {
    unsigned h0,h1,h2,h3,h4,h5,h6,h7, l0,l1,l2,l3,l4,l5,l6,l7;
    bsplit(a.x,h0,l0); bsplit(a.y,h1,l1); bsplit(a.z,h2,l2); bsplit(a.w,h3,l3);
    bsplit(b.x,h4,l4); bsplit(b.y,h5,l5); bsplit(b.z,h6,l6); bsplit(b.w,h7,l7);
    H.x = h0 | (h1<<16); H.y = h2 | (h3<<16); H.z = h4 | (h5<<16); H.w = h6 | (h7<<16);
    L.x = l0 | (l1<<16); L.y = l2 | (l3<<16); L.z = l4 | (l5<<16); L.w = l6 | (l7<<16);
}

// ---------------- HMMA GEMM: C = epi(A[M,K] @ B[Nn,K]^T) ----------------
// AMODE 0: A f32 gmem. AMODE 1: A preconverted bf16 hi/lo. AMODE 2: fused pairs.
// Warp grid WR x WC (8 warps), block tile (WR*32) x (WC*32). K-step 32, bf16 hi/lo
// 3-pass. gridDim.z splits K; partial z writes to C + z*zstride (no bias/relu then).
template<int AMODE, int WR, int WC>
__global__ void __launch_bounds__(256) tgemm(
    const float* __restrict__ A, int lda,
    const __nv_bfloat16* __restrict__ Ahi_g, const __nv_bfloat16* __restrict__ Alo_g, int ldabf,
    const float* __restrict__ B, int ldb,
    const float* __restrict__ bias_n, const float* __restrict__ rowt,
    float* __restrict__ C, int M, int Nn, int K, int relu, long zstride)
{
    constexpr int BM = WR*32, BN = WC*32;
    constexpr int ALOo = BM*80, BHIo = BM*160, BLOo = BM*160 + BN*80;
    constexpr int BUFSZ = (BM + BN) * 160;
    constexpr int NSEGA = BM / 64;             // A segs (8 cols) per thread
    extern __shared__ char smem[];
    uint32_t sbase = smem_u32(smem);

    int tid = threadIdx.x, lane = tid & 31, wid = tid >> 5;
    int wm = wid % WR, wn = wid / WR;
    int m0 = blockIdx.y * BM, n0 = blockIdx.x * BN;

    int nk = (K + 31) >> 5;
    int chunk = (nk + gridDim.z - 1) / gridDim.z;
    int ks0 = blockIdx.z * chunk;
    int ks1 = min(nk, ks0 + chunk);
    float* Cz = C + (size_t)blockIdx.z * zstride;

    // ---- hoisted A addressing ----
    int arow[NSEGA], asegc[NSEGA];
    bool aok[NSEGA];
    const float *apf[NSEGA], *apf2[NSEGA];
    const __nv_bfloat16 *aph[NSEGA], *apl[NSEGA];
    #pragma unroll
    for (int s = 0; s < NSEGA; s++) {
        int idx = tid + s * 256;
        arow[s] = idx >> 2; asegc[s] = idx & 3;
        int gm = m0 + arow[s];
        aok[s] = true; apf[s] = nullptr; apf2[s] = nullptr; aph[s] = nullptr; apl[s] = nullptr;
        if (AMODE == 0) { aok[s] = gm < M; apf[s] = A + (size_t)(aok[s] ? gm : 0) * lda; }
        if (AMODE == 1) { aph[s] = Ahi_g + (size_t)gm * ldabf; apl[s] = Alo_g + (size_t)gm * ldabf; }
        if (AMODE == 2) {
            int b = gm / PP, p = gm - b * PP;
            apf[s]  = d_Aq + (size_t)(b * 32 + d_pi[p]) * Q1S;
            apf2[s] = d_Bq + (size_t)(b * 32 + d_pj[p]) * Q1S;
        }
    }
    // ---- hoisted B addressing ----
    int brow = tid >> 2, bsegc = tid & 3;
    bool bact = (tid < BN * 4);
    bool bok = bact && (n0 + brow) < Nn;
    const float* bp = B + (size_t)(bok ? (n0 + brow) : 0) * ldb;

    // staging regs
    float4 sa0[NSEGA], sa1[NSEGA], sb0, sb1;
    uint4 sH[NSEGA], sL[NSEGA];
    const float4 f4z = make_float4(0.f, 0.f, 0.f, 0.f);
    sb0 = f4z; sb1 = f4z;

    auto load_regs = [&](int ik) {
        int kg = ik * 32;
        #pragma unroll
        for (int s = 0; s < NSEGA; s++) {
            int gk = kg + asegc[s] * 8;
            if (AMODE == 1) {
                sH[s] = *(const uint4*)(aph[s] + gk);
                sL[s] = *(const uint4*)(apl[s] + gk);
            } else if (AMODE == 0) {
                sa0[s] = (aok[s] && gk < K)     ? *(const float4*)(apf[s] + gk)     : f4z;
                sa1[s] = (aok[s] && gk + 4 < K) ? *(const float4*)(apf[s] + gk + 4) : f4z;
            } else {
                if (gk < K) {
                    float4 u = *(const float4*)(apf[s] + gk), v = *(const float4*)(apf2[s] + gk);
                    sa0[s] = make_float4(fmaxf(u.x+v.x,0.f), fmaxf(u.y+v.y,0.f),
                                         fmaxf(u.z+v.z,0.f), fmaxf(u.w+v.w,0.f));
                } else sa0[s] = f4z;
                if (gk + 4 < K) {
                    float4 u = *(const float4*)(apf[s] + gk + 4), v = *(const float4*)(apf2[s] + gk + 4);
                    sa1[s] = make_float4(fmaxf(u.x+v.x,0.f), fmaxf(u.y+v.y,0.f),
                                         fmaxf(u.z+v.z,0.f), fmaxf(u.w+v.w,0.f));
                } else sa1[s] = f4z;
            }
        }
        if (bact) {
            int gk = kg + bsegc * 8;
            sb0 = (bok && gk < K)     ? *(const float4*)(bp + gk)     : f4z;
            sb1 = (bok && gk + 4 < K) ? *(const float4*)(bp + gk + 4) : f4z;
        }
    };
    auto conv_store = [&](char* buf) {
        #pragma unroll
        for (int s = 0; s < NSEGA; s++) {
            uint4 H, L;
            if (AMODE == 1) { H = sH[s]; L = sL[s]; }
            else conv8(sa0[s], sa1[s], H, L);
            *(uint4*)(buf + arow[s]*80 + asegc[s]*16) = H;
            *(uint4*)(buf + ALOo + arow[s]*80 + asegc[s]*16) = L;
        }
        if (bact) {
            uint4 H, L; conv8(sb0, sb1, H, L);
            *(uint4*)(buf + BHIo + brow*80 + bsegc*16) = H;
            *(uint4*)(buf + BLOo + brow*80 + bsegc*16) = L;
        }
    };

    // ldmatrix lane offsets (bytes)
    uint32_t aoff[2], boff[4];
    #pragma unroll
    for (int mt = 0; mt < 2; mt++)
        aoff[mt] = (uint32_t)(((wm*32 + mt*16 + (lane & 15)) * 40 + ((lane >> 4) & 1) * 8) * 2);
    #pragma unroll
    for (int nt = 0; nt < 4; nt++)
        boff[nt] = (uint32_t)(((wn*32 + nt*8 + (lane & 7)) * 40 + ((lane >> 3) & 1) * 8) * 2);

    float acc[2][4][4];
    #pragma unroll
    for (int mt = 0; mt < 2; mt++)
        #pragma unroll
        for (int nt = 0; nt < 4; nt++)
            #pragma unroll
            for (int q = 0; q < 4; q++) acc[mt][nt][q] = 0.f;

    // ---- pipelined main loop ----
    load_regs(ks0);
    conv_store(smem);
    __syncthreads();
    for (int i = ks0; i < ks1; i++) {
        bool more = (i + 1 < ks1);
        if (more) load_regs(i + 1);
        uint32_t tb = sbase + ((i - ks0) & 1) * BUFSZ;
        #pragma unroll
        for (int kh = 0; kh < 2; kh++) {
            uint32_t ah[2][4], al[2][4], bh[4][2], bl[4][2];
            #pragma unroll
            for (int mt = 0; mt < 2; mt++) {
                ldsm4(ah[mt], tb + aoff[mt] + kh*32);
                ldsm4(al[mt], tb + ALOo + aoff[mt] + kh*32);
            }
            #pragma unroll
            for (int nt = 0; nt < 4; nt++) {
                ldsm2(bh[nt], tb + BHIo + boff[nt] + kh*32);
                ldsm2(bl[nt], tb + BLOo + boff[nt] + kh*32);
            }
            #pragma unroll
            for (int mt = 0; mt < 2; mt++)
                #pragma unroll
                for (int nt = 0; nt < 4; nt++) {
                    mma16816(acc[mt][nt], ah[mt], bh[nt]);
                    mma16816(acc[mt][nt], ah[mt], bl[nt]);
                    mma16816(acc[mt][nt], al[mt], bh[nt]);
                }
        }
        if (more) conv_store(smem + ((i + 1 - ks0) & 1) * BUFSZ);
        __syncthreads();
    }

    // ---- epilogue ----
    #pragma unroll
    for (int mt = 0; mt < 2; mt++) {
        #pragma unroll
        for (int half = 0; half < 2; half++) {
            int gm = m0 + wm*32 + mt*16 + (lane >> 2) + half*8;
            if (gm >= M) continue;
            int bidx = gm / PP;
            float* crow = Cz + (size_t)gm * Nn;
            #pragma unroll
            for (int nt = 0; nt < 4; nt++) {
                int gn = n0 + wn*32 + nt*8 + (lane & 3) * 2;
                if (gn >= Nn) continue;
                float v0 = acc[mt][nt][half*2+0];
                float v1 = acc[mt][nt][half*2+1];
                bool o1 = (gn + 1 < Nn);
                if (bias_n) { v0 += bias_n[gn]; if (o1) v1 += bias_n[gn+1]; }
                if (rowt)   { v0 += rowt[(size_t)gn*32 + bidx]; if (o1) v1 += rowt[(size_t)(gn+1)*32 + bidx]; }
                if (relu)   { v0 = fmaxf(v0, 0.f); v1 = fmaxf(v1, 0.f); }
                crow[gn] = v0;
                if (o1) crow[gn+1] = v1;
            }
        }
    }
}

// ---------------- sort ----------------
__global__ void k_sort(const float* __restrict__ x) {
    int tid = blockIdx.x * blockDim.x + threadIdx.x;
    int b = tid >> 8, e = tid & 255;
    float v[32];
    #pragma unroll
    for (int t = 0; t < 32; t++) v[t] = x[(b * 32 + t) * EE + e];
    for (int a = 1; a < 32; a++) {
        float key = v[a];
        int c = a - 1;
        while (c >= 0 && v[c] > key) { v[c + 1] = v[c]; c--; }
        v[c + 1] = key;
    }
    #pragma unroll
    for (int t = 0; t < 32; t++) d_S[(t * 32 + b) * EE + e] = v[t];
}

// ---------------- init ----------------
__global__ void k_init(const float* __restrict__ q1_w, const float* __restrict__ q1_b) {
    int idx = blockIdx.x * blockDim.x + threadIdx.x;
    if (idx < PP) {
        int p = idx, i = 0, cnt = 31;
        while (p >= cnt) { p -= cnt; i++; cnt--; }
        d_pi[idx] = i; d_pj[idx] = i + 1 + p;
    } else if (idx < PP + Q1S) {
        int o = idx - PP;
        float s = q1_b[o];
        for (int d = 1; d < 2 * EE; d += 2) s += q1_w[o * (2 * EE) + d];
        d_q1beff[o] = s;
    } else {
        int z = idx - (PP + Q1S);
        if (z < BB * HH)           d_h[0][z] = 0.f;
        else if (z < 2 * BB * HH)  d_h[1][z - BB * HH] = 0.f;
        else if (z < 3 * BB * HH)  d_cT[z - 2 * BB * HH] = 0.f;
    }
}

// ---------------- preconvert w_hh -> bf16 hi/lo [6144][1536] ----------------
__global__ void k_convw(const float* __restrict__ w) {
    size_t idx = (size_t)blockIdx.x * blockDim.x + threadIdx.x;
    if (idx >= (size_t)G4P * KHP) return;
    int r = (int)(idx / KHP), c = (int)(idx - (size_t)r * KHP);
    float v = (r < G4 && c < HH) ? w[(size_t)r * HH + c] : 0.f;
    __nv_bfloat16 bh = __float2bfloat16_rn(v);
    d_whh_hi[idx] = bh;
    d_whh_lo[idx] = __float2bfloat16_rn(v - __bfloat162float(bh));
}

// ---------------- LSTM gate/state update ----------------
__global__ void lstm_combine_T(int t, const float* __restrict__ b_ih,
                               const float* __restrict__ b_hh) {
    int idx = blockIdx.x * blockDim.x + threadIdx.x;
    if (idx >= BB * HH) return;
    int j = idx >> 5, b = idx & 31;
    float g[4];
    #pragma unroll
    for (int gg = 0; gg < 4; gg++) {
        int r = gg * HH + j;
        float v = d_xp[(size_t)r * MNB + t * 32 + b] + b_ih[r] + b_hh[r];
        #pragma unroll
        for (int z = 0; z < 4; z++) v += d_gpart4[z][r * 32 + b];
        g[gg] = v;
    }
    float ci = 1.f / (1.f + expf(-g[0]));
    float cf = 1.f / (1.f + expf(-g[1]));
    float cg = tanhf(g[2]);
    float co = 1.f / (1.f + expf(-g[3]));
    float cn = cf * d_cT[idx] + ci * cg;
    d_cT[idx] = cn;
    d_h[(t + 1) & 1][b * HH + j] = co * tanhf(cn);
}

// ---------------- pt combine: sum 4 partials + e1_b ----------------
__global__ void k_ptcomb(const float* __restrict__ e1_b) {
    int idx = blockIdx.x * blockDim.x + threadIdx.x;
    if (idx >= EV1S * BB) return;
    int n = idx >> 5;
    float v = e1_b[n];
    #pragma unroll
    for (int z = 0; z < 4; z++) v += d_pt4[z][idx];
    d_ptT[idx] = v;
}

// ---------------- tail: e3 + e4 fused ----------------
__global__ void k_tail(const float* __restrict__ e3w, const float* __restrict__ e3b,
                       const float* __restrict__ e4w, const float* __restrict__ e4b,
                       float* __restrict__ out)
{
    __shared__ float s2[64][101];
    __shared__ float sw[10][100];
    __shared__ float sb[10], s4[10];
    __shared__ float s4b;
    int m0 = blockIdx.x * 64;
    int tid = threadIdx.x;  // 64
    for (int l = 0; l < 100; l++) {
        int idx = tid + l * 64;
        s2[idx / 100][idx % 100] = d_e2buf[(size_t)m0 * EV2S + idx];
    }
    if (tid < 10) { sb[tid] = e3b[tid]; s4[tid] = e4w[tid]; }
    if (tid == 0) s4b = e4b[0];
    for (int l = tid; l < 1000; l += 64) sw[l / 100][l % 100] = e3w[l];
    __syncthreads();
    float acc = s4b;
    #pragma unroll
    for (int g = 0; g < 10; g++) {
        float a = sb[g];
        #pragma unroll 4
        for (int k = 0; k < 100; k++) a = fmaf(s2[tid][k], sw[g][k], a);
        acc = fmaf(fmaxf(a, 0.f), s4[g], acc);
    }
    out[m0 + tid] = fmaxf(acc, 0.f);
}

// ---------------- launch ----------------
#define SM42 ((128+64)*160*2)   // 61440
#define SM81 ((256+32)*160*2)   // 92160

extern "C" void kernel_launch(void* const* d_in, const int* in_sizes, int n_in,
                              void* d_out, int out_size)
{
    const float* x    = (const float*)d_in[0];
    const float* w_ih = (const float*)d_in[1];
    const float* w_hh = (const float*)d_in[2];
    const float* b_ih = (const float*)d_in[3];
    const float* b_hh = (const float*)d_in[4];
    const float* q1_w = (const float*)d_in[5];
    const float* q1_b = (const float*)d_in[6];
    const float* q2_w = (const float*)d_in[7];
    const float* q2_b = (const float*)d_in[8];
    const float* e1_w = (const float*)d_in[9];
    const float* e1_b = (const float*)d_in[10];
    const float* e2_w = (const float*)d_in[11];
    const float* e2_b = (const float*)d_in[12];
    const float* e3_w = (const float*)d_in[13];
    const float* e3_b = (const float*)d_in[14];
    const float* e4_w = (const float*)d_in[15];
    const float* e4_b = (const float*)d_in[16];
    float* out = (float*)d_out;

    cudaFuncSetAttribute(tgemm<0,4,2>, cudaFuncAttributeMaxDynamicSharedMemorySize, SM42);
    cudaFuncSetAttribute(tgemm<2,4,2>, cudaFuncAttributeMaxDynamicSharedMemorySize, SM42);
    cudaFuncSetAttribute(tgemm<1,8,1>, cudaFuncAttributeMaxDynamicSharedMemorySize, SM81);
    cudaFuncSetAttribute(tgemm<0,8,1>, cudaFuncAttributeMaxDynamicSharedMemorySize, SM81);

    float *pS, *pXp, *pH0, *pH1, *pGp, *pQb, *pAq, *pBq, *pPt4, *pPt, *pQ2, *pE1, *pE2;
    __nv_bfloat16 *pWh, *pWl;
    cudaGetSymbolAddress((void**)&pS,   d_S);
    cudaGetSymbolAddress((void**)&pXp,  d_xp);
    cudaGetSymbolAddress((void**)&pH0,  d_h);
    pH1 = pH0 + BB * HH;
    cudaGetSymbolAddress((void**)&pGp,  d_gpart4);
    cudaGetSymbolAddress((void**)&pPt4, d_pt4);
    cudaGetSymbolAddress((void**)&pPt,  d_ptT);
    cudaGetSymbolAddress((void**)&pQb,  d_q1beff);
    cudaGetSymbolAddress((void**)&pAq,  d_Aq);
    cudaGetSymbolAddress((void**)&pBq,  d_Bq);
    cudaGetSymbolAddress((void**)&pQ2,  d_q2);
    cudaGetSymbolAddress((void**)&pE1,  d_e1buf);
    cudaGetSymbolAddress((void**)&pE2,  d_e2buf);
    cudaGetSymbolAddress((void**)&pWh,  d_whh_hi);
    cudaGetSymbolAddress((void**)&pWl,  d_whh_lo);

    // 1. sort + init + whh preconvert
    k_sort<<<32, 256>>>(x);
    k_init<<<(PP + Q1S + 3 * BB * HH + 255) / 256, 256>>>(q1_w, q1_b);
    k_convw<<<(int)(((size_t)G4P * KHP + 255) / 256), 256>>>(w_hh);

    // 2. xp = w_ih @ S^T -> [6000][1024]
    tgemm<0,4,2><<<dim3(16, 47, 1), 256, SM42>>>(
        w_ih, EE, nullptr, nullptr, 0, pS, EE,
        nullptr, nullptr, pXp, G4, MNB, EE, 0, 0);
    // 3. factored q1 halves -> [1024][600]
    tgemm<0,4,2><<<dim3(10, 8, 1), 256, SM42>>>(
        x, EE, nullptr, nullptr, 0, q1_w, 2 * EE,
        pQb, nullptr, pAq, MNB, Q1S, EE, 0, 0);
    tgemm<0,4,2><<<dim3(10, 8, 1), 256, SM42>>>(
        x, EE, nullptr, nullptr, 0, q1_w + EE, 2 * EE,
        nullptr, nullptr, pBq, MNB, Q1S, EE, 0, 0);

    // 4. LSTM recurrence: gpart4[z] = (whh @ h^T) K-chunks -> combine
    for (int t = 0; t < 32; t++) {
        const float* hprev = (t & 1) ? pH1 : pH0;
        tgemm<1,8,1><<<dim3(1, 24, 4), 256, SM81>>>(
            nullptr, 0, pWh, pWl, KHP, hprev, HH,
            nullptr, nullptr, pGp, G4, BB, HH, 0, (long)G4P * BB);
        lstm_combine_T<<<(BB * HH + 255) / 256, 256>>>(t, b_ih, b_hh);
    }

    // 5. pt partials + combine (folds e1_b)
    tgemm<0,8,1><<<dim3(1, 4, 4), 256, SM81>>>(
        e1_w, HH + QS, nullptr, nullptr, 0, pH0, HH,
        nullptr, nullptr, pPt4, EV1S, BB, HH, 0, (long)PTP * BB);
    k_ptcomb<<<(EV1S * BB + 255) / 256, 256>>>(e1_b);

    // 6. q2 with fused pair construction -> [15872][300]
    tgemm<2,4,2><<<dim3(5, 124, 1), 256, SM42>>>(
        nullptr, 0, nullptr, nullptr, 0, q2_w, Q1S,
        q2_b, nullptr, pQ2, MPAIR, QS, Q1S, 1, 0);

    // 7. e1 = relu(q2 @ e1_wQ^T + ptT) -> [15872][1000]
    tgemm<0,4,2><<<dim3(16, 124, 1), 256, SM42>>>(
        pQ2, QS, nullptr, nullptr, 0, e1_w + HH, HH + QS,
        nullptr, pPt, pE1, MPAIR, EV1S, QS, 1, 0);

    // 8. e2 -> [15872][100]
    tgemm<0,4,2><<<dim3(2, 124, 1), 256, SM42>>>(
        pE1, EV1S, nullptr, nullptr, 0, e2_w, EV1S,
        e2_b, nullptr, pE2, MPAIR, EV2S, EV1S, 1, 0);

    // 9. e3+e4 fused tail
    k_tail<<<MPAIR / 64, 64>>>(e3_w, e3_b, e4_w, e4_b, out);
}